// round 10
// baseline (speedup 1.0000x reference)
#include <cuda_runtime.h>
#include <cuda_fp16.h>
#include <cstdint>
#include <cstddef>

#define HWD  224
#define CIN  256
#define FOUT 256
#define OBS  14
#define KTOT 2304            // 9 taps * 256 c
#define NSTG 12              // 4 chunks * 3 stages; stage = 3 taps * 4 k16-steps

// smem layout (bytes)
#define WIN0   0             // two 16x16x64c fp16 windows (32 KB each)
#define BOFF   65536         // 3 cyclic B buffers, 48 KB each (3 taps x 16 KB)
#define BIASOF 212992        // 512 B
#define REDOF  213504        // mask-reduce scratch (64B sums + flag)
#define SMEM_TOTAL 213632

__device__ __align__(16) __half g_W2[256 * KTOT];   // [f][tap*256 + c]

__device__ __forceinline__ uint32_t smem_to_u32(const void* p) {
    uint32_t a;
    asm("{ .reg .u64 t; cvta.to.shared.u64 t, %1; cvt.u32.u64 %0, t; }" : "=r"(a) : "l"(p));
    return a;
}

#define LDSM4(r0, r1, r2, r3, addr) \
    asm volatile("ldmatrix.sync.aligned.m8n8.x4.shared.b16 {%0,%1,%2,%3}, [%4];" \
        : "=r"(r0), "=r"(r1), "=r"(r2), "=r"(r3) : "r"(addr))

#define MMA16816(d, a0, a1, a2, a3, b0, b1) \
    asm volatile("mma.sync.aligned.m16n8k16.row.col.f32.f16.f16.f32 " \
        "{%0,%1,%2,%3}, {%4,%5,%6,%7}, {%8,%9}, {%0,%1,%2,%3};" \
        : "+f"((d)[0]), "+f"((d)[1]), "+f"((d)[2]), "+f"((d)[3]) \
        : "r"(a0), "r"(a1), "r"(a2), "r"(a3), "r"(b0), "r"(b1))

#define CP_ASYNC16(dst, src) \
    asm volatile("cp.async.cg.shared.global [%0], [%1], 16;" \
        :: "r"((uint32_t)(dst)), "l"(src) : "memory")
#define CP_COMMIT() asm volatile("cp.async.commit_group;" ::: "memory")
#define CP_WAIT1()  asm volatile("cp.async.wait_group 1;" ::: "memory")

// ---------------------------------------------------------------------------
// Weight transpose to fp16: g_W2[f][k], k = tap*256 + c
// ---------------------------------------------------------------------------
__global__ void wprep_kernel(const float* __restrict__ wgt) {
    int idx = blockIdx.x * 256 + threadIdx.x;
    int f = idx & 255;
    int k = idx >> 8;
    g_W2[(size_t)f * KTOT + k] = __float2half_rn(wgt[(size_t)k * 256 + f]);
}

// ---------------------------------------------------------------------------
// Pipelined per-tap compute: 4 k16-steps; NT m-tiles (4 or 3, compile-time).
// B ldmatrix first, then A(j+1) prefetched under A(j)'s 4 MMAs.
// ---------------------------------------------------------------------------
template<int NT>
__device__ __forceinline__ void compute_tap(
    float acc[4][4][4],
    uint32_t winb, uint32_t btap,
    const uint32_t* __restrict__ arow, const uint32_t* __restrict__ ap7,
    const uint32_t* __restrict__ brow, const uint32_t* __restrict__ bp7,
    int acgl, int bg0)
{
    #pragma unroll
    for (int kk = 0; kk < 4; ++kk) {
        uint32_t bfr[2][4];
        int bcg = 2 * kk + bg0;
        #pragma unroll
        for (int u = 0; u < 2; ++u) {
            uint32_t ba = btap + brow[u] + (uint32_t)(((bcg ^ bp7[u])) << 4);
            LDSM4(bfr[u][0], bfr[u][1], bfr[u][2], bfr[u][3], ba);
        }
        int acg = 2 * kk + acgl;
        uint32_t a0, a1, a2, a3;
        {
            uint32_t aa = winb + arow[0] + (uint32_t)(((acg ^ ap7[0])) << 4);
            LDSM4(a0, a1, a2, a3, aa);
        }
        #pragma unroll
        for (int j = 0; j < NT; ++j) {
            uint32_t n0, n1, n2, n3;
            if (j + 1 < NT) {
                uint32_t aa = winb + arow[j + 1] + (uint32_t)(((acg ^ ap7[j + 1])) << 4);
                LDSM4(n0, n1, n2, n3, aa);
            }
            MMA16816(acc[j][0], a0, a1, a2, a3, bfr[0][0], bfr[0][1]);
            MMA16816(acc[j][1], a0, a1, a2, a3, bfr[0][2], bfr[0][3]);
            MMA16816(acc[j][2], a0, a1, a2, a3, bfr[1][0], bfr[1][1]);
            MMA16816(acc[j][3], a0, a1, a2, a3, bfr[1][2], bfr[1][3]);
            if (j + 1 < NT) { a0 = n0; a1 = n1; a2 = n2; a3 = n3; }
        }
    }
}

// ---------------------------------------------------------------------------
// Conv kernel: per (block, 128-filter half), 512 threads / 16 warps.
// wc = warp&3 (n32) => SMSP carries 4/3/3/3 m-groups = 13 tiles, balanced.
// wr = warp>>2: m-tile bases {0,4,7,10}, sizes {4,3,3,3}.
// ---------------------------------------------------------------------------
__global__ void __launch_bounds__(512, 1)
conv_mma_kernel(const float* __restrict__ in, const float* __restrict__ mask,
                const float* __restrict__ bias, float* __restrict__ out) {
    int b = blockIdx.x;
    int fhalf = blockIdx.y;
    int nb = b >> 8, by = (b >> 4) & 15, bx = b & 15;
    int tid = threadIdx.x;
    int fbase = fhalf * 128;

    extern __shared__ char smem[];
    uint32_t sbase = smem_to_u32(smem);

    // ---- activity test (pooled mask mean > 0.5); threads 0-255 sample ----
    {
        double* sred = (double*)(smem + REDOF);
        int* sflag = (int*)(smem + REDOF + 64);
        if (tid < 256) {
            int ty = tid >> 4, tx = tid & 15;
            int h = by * OBS - 1 + ty;
            int w = bx * OBS - 1 + tx;
            float v = 0.f;
            if ((unsigned)h < HWD && (unsigned)w < HWD)
                v = mask[(nb * HWD + h) * HWD + w];
            double d = (double)v;
            #pragma unroll
            for (int o = 16; o > 0; o >>= 1)
                d += __shfl_down_sync(0xffffffffu, d, o);
            if ((tid & 31) == 0) sred[tid >> 5] = d;
        }
        __syncthreads();
        if (tid == 0) {
            double s = 0.0;
            #pragma unroll
            for (int i = 0; i < 8; ++i) s += sred[i];
            *sflag = (s * (1.0 / 256.0) > 0.5) ? 1 : 0;
        }
        __syncthreads();
        if (!*sflag) {
            if (tid < 196) {
                int Y = by * OBS + tid / OBS, X = bx * OBS + tid % OBS;
                float4* o = (float4*)(out + (((size_t)nb * HWD + Y) * HWD + X) * FOUT + fbase);
                float4 z = make_float4(0.f, 0.f, 0.f, 0.f);
                #pragma unroll
                for (int i = 0; i < 32; ++i) o[i] = z;
            }
            return;
        }
    }

    int warp = tid >> 5, lane = tid & 31;
    int wc = warp & 3;            // n column-group (n32), = SMSP id
    int wr = warp >> 2;           // m row-group
    int mtb = (wr == 0) ? 0 : (3 * wr + 1);   // 0,4,7,10

    if (tid < 32) ((float4*)(smem + BIASOF))[tid] = ((const float4*)(bias + fbase))[tid];

    // per-lane A-row table (window pixel index per m-tile, pre-halo)
    int P0[4];
    {
        int mrow = (lane & 7) + ((lane >> 3) & 1) * 8;
        #pragma unroll
        for (int j = 0; j < 4; ++j) {
            int mt = mtb + j;
            if (mt > 12) mt = 12;
            int m = mt * 16 + mrow;
            if (m > 195) m = 195;
            int py = m / 14, px = m - py * 14;
            P0[j] = (py + 1) * 16 + (px + 1);
        }
    }
    int acgl = (lane >> 4) & 1;
    int bnl  = ((lane >> 4) & 1) * 8 + (lane & 7);
    int bg0  = (lane >> 3) & 1;

    uint32_t brow[2], bp7[2];
    #pragma unroll
    for (int u = 0; u < 2; ++u) {
        int bn = wc * 32 + u * 16 + bnl;
        brow[u] = (uint32_t)bn * 128;
        bp7[u]  = (uint32_t)(bn & 7);
    }

    float acc[4][4][4];
    #pragma unroll
    for (int j = 0; j < 4; ++j)
        #pragma unroll
        for (int t = 0; t < 4; ++t)
            #pragma unroll
            for (int e = 0; e < 4; ++e) acc[j][t][e] = 0.f;

    const float* inb = in + (size_t)nb * HWD * HWD * CIN;
    int h0 = by * OBS - 1;
    int w0 = bx * OBS - 1;

    // window loader: 2048 uint4 units over 512 threads (4 each)
    auto load_window = [&](int cc, int wb) {
        int c0 = cc * 64;
        char* wdst = smem + WIN0 + wb * 32768;
        #pragma unroll
        for (int j = 0; j < 4; ++j) {
            int u = tid + j * 512;
            int p = u >> 3, g = u & 7;
            int y = p >> 4, x = p & 15;
            int gy = h0 + y, gx = w0 + x;
            float v[8];
            #pragma unroll
            for (int e = 0; e < 8; ++e) v[e] = 0.f;
            if ((unsigned)gy < HWD && (unsigned)gx < HWD) {
                const float* sp = inb + (((size_t)gy * HWD + gx) * CIN) + c0 + g * 8;
                float4 va = ((const float4*)sp)[0];
                float4 vb = ((const float4*)sp)[1];
                v[0] = va.x; v[1] = va.y; v[2] = va.z; v[3] = va.w;
                v[4] = vb.x; v[5] = vb.y; v[6] = vb.z; v[7] = vb.w;
            }
            union { __half hf[8]; uint4 u4; } H;
            #pragma unroll
            for (int e = 0; e < 8; ++e) H.hf[e] = __float2half_rn(v[e]);
            *(uint4*)(wdst + p * 128 + (((g ^ (p & 7))) << 4)) = H.u4;
        }
    };

    // B stage issuer: 3072 x 16B over 512 threads (6 cp.async each)
    auto issue_B = [&](int t) {
        int cct = t / 3, tbt = (t % 3) * 3;
        uint32_t bufb = sbase + BOFF + (uint32_t)(t % 3) * 49152;
        const __half* wsrc = g_W2 + tbt * 256 + cct * 64;
        #pragma unroll
        for (int j = 0; j < 6; ++j) {
            int u = tid + j * 512;
            int tl = u >> 10;
            int rem = u & 1023;
            int n = rem >> 3, g = rem & 7;
            const __half* src = wsrc + (size_t)(fbase + n) * KTOT + tl * 256 + g * 8;
            uint32_t dst = bufb + tl * 16384 + n * 128 + (((g ^ (n & 7))) << 4);
            CP_ASYNC16(dst, src);
        }
    };

    // prologue: B(0) in flight, window chunk 0 into winbuf 0
    issue_B(0);
    CP_COMMIT();
    load_window(0, 0);

    for (int s = 0; s < NSTG; ++s) {
        int cc = s / 3;
        int tb = (s % 3) * 3;

        if (s + 1 < NSTG) issue_B(s + 1);
        CP_COMMIT();
        CP_WAIT1();            // B(s) complete locally
        __syncthreads();       // publish B(s) + window/bias STS; compute(s-1) done

        // prefetch next chunk's window into the other winbuf
        if ((s % 3) == 2 && cc + 1 < 4) load_window(cc + 1, (cc + 1) & 1);

        uint32_t winb = sbase + WIN0 + (uint32_t)(cc & 1) * 32768;
        uint32_t bbuf = sbase + BOFF + (uint32_t)(s % 3) * 49152;

        #pragma unroll
        for (int tl = 0; tl < 3; ++tl) {
            int tap = tb + tl;
            int dy = tap / 3 - 1, dx = tap - (tap / 3) * 3 - 1;
            int doff = dy * 16 + dx;
            uint32_t btap = bbuf + tl * 16384;

            uint32_t arow[4], ap7[4];
            #pragma unroll
            for (int j = 0; j < 4; ++j) {
                int P = P0[j] + doff;
                arow[j] = (uint32_t)P * 128;
                ap7[j]  = (uint32_t)(P & 7);
            }
            if (wr == 0)
                compute_tap<4>(acc, winb, btap, arow, ap7, brow, bp7, acgl, bg0);
            else
                compute_tap<3>(acc, winb, btap, arow, ap7, brow, bp7, acgl, bg0);
        }
    }

    // ---- epilogue: bias + relu + store ----
    const float* sb = (const float*)(smem + BIASOF);
    int NTe = (wr == 0) ? 4 : 3;
    #pragma unroll
    for (int j = 0; j < 4; ++j) {
        if (j < NTe) {
            int mt = mtb + j;
            #pragma unroll
            for (int u = 0; u < 2; ++u) {
                #pragma unroll
                for (int hf = 0; hf < 2; ++hf) {
                    int nn = wc * 32 + u * 16 + hf * 8 + (lane & 3) * 2;
                    float bz0 = sb[nn], bz1 = sb[nn + 1];
                    #pragma unroll
                    for (int h2 = 0; h2 < 2; ++h2) {
                        int m = mt * 16 + (lane >> 2) + h2 * 8;
                        if (m < 196) {
                            int py = m / 14, px = m - py * 14;
                            float* o = out + (((size_t)nb * HWD + by * OBS + py) * HWD
                                              + bx * OBS + px) * FOUT + fbase + nn;
                            float2 v;
                            v.x = fmaxf(acc[j][u * 2 + hf][h2 * 2 + 0] + bz0, 0.f);
                            v.y = fmaxf(acc[j][u * 2 + hf][h2 * 2 + 1] + bz1, 0.f);
                            *(float2*)o = v;
                        }
                    }
                }
            }
        }
    }
}

extern "C" void kernel_launch(void* const* d_in, const int* in_sizes, int n_in,
                              void* d_out, int out_size) {
    (void)in_sizes; (void)n_in; (void)out_size;
    const float* in   = (const float*)d_in[0];   // (4,224,224,256)
    const float* mask = (const float*)d_in[1];   // (4,224,224,1)
    const float* wgt  = (const float*)d_in[2];   // (3,3,256,256)
    const float* bias = (const float*)d_in[3];   // (256,)
    float* out = (float*)d_out;

    cudaFuncSetAttribute(conv_mma_kernel,
                         cudaFuncAttributeMaxDynamicSharedMemorySize, SMEM_TOTAL);
    wprep_kernel<<<2304, 256>>>(wgt);
    dim3 grid(1024, 2);
    conv_mma_kernel<<<grid, 512, SMEM_TOTAL>>>(in, mask, bias, out);
}